// round 7
// baseline (speedup 1.0000x reference)
#include <cuda_runtime.h>
#include <cuda_fp16.h>
#include <stdint.h>
#include <math.h>

#define B_    64
#define I_    48
#define O_    48
#define F_    256
#define H_    256
#define FIVEH 1280
#define NCTA  144               // 18 cell-slots x 8 htiles

// smem: resident W' slab (8 k-chunks x 160 rows x 144B) + A double buffer
#define WCH    23040            // 160*144
#define W_TOT  (8*WCH)          // 184320
#define APASS  9216             // 64 rows * 144B
#define ASTAGE (2*APASS)        // hi+lo = 18432
#define SMEM_TOTAL (W_TOT + 2*ASTAGE)   // 221184

// ---------------- scratch (device globals) ----------------------------------
__device__ float g_PX[I_ * B_ * FIVEH];          // [i][b][g*256+h]
__device__ float g_PY[O_ * B_ * FIVEH];
__device__ __half g_Wh[FIVEH * 512];             // W' fp16, [n'][k], n'=h*5+g
__device__ __half g_Shi[2][I_ * B_ * H_];
__device__ __half g_Slo[2][I_ * B_ * H_];
__device__ float  g_C[2][I_ * B_ * H_];
__device__ unsigned g_count;
__device__ unsigned g_epoch;

__device__ __forceinline__ float sigf(float x) { return 1.0f / (1.0f + expf(-x)); }

__device__ __forceinline__ uint32_t smem_u32(const void* p) {
    uint32_t a;
    asm("{ .reg .u64 t; cvta.to.shared.u64 t, %1; cvt.u32.u64 %0, t; }" : "=r"(a) : "l"(p));
    return a;
}
__device__ __forceinline__ void cp16(uint32_t dst, const void* src) {
    asm volatile("cp.async.cg.shared.global [%0], [%1], 16;"
                 :: "r"(dst), "l"(src) : "memory");
}
#define CP_COMMIT() asm volatile("cp.async.commit_group;" ::: "memory")
#define CP_WAIT(n)  asm volatile("cp.async.wait_group %0;" :: "n"(n) : "memory")

__device__ __forceinline__ void ldmA(uint32_t* a, uint32_t addr) {
    asm volatile("ldmatrix.sync.aligned.m8n8.x4.shared.b16 {%0,%1,%2,%3}, [%4];"
                 : "=r"(a[0]), "=r"(a[1]), "=r"(a[2]), "=r"(a[3]) : "r"(addr));
}
__device__ __forceinline__ void ldmB(uint32_t* b, uint32_t addr) {
    asm volatile("ldmatrix.sync.aligned.m8n8.x2.shared.b16 {%0,%1}, [%2];"
                 : "=r"(b[0]), "=r"(b[1]) : "r"(addr));
}
__device__ __forceinline__ void mma16816(float* c, const uint32_t* a, const uint32_t* b) {
    asm volatile("mma.sync.aligned.m16n8k16.row.col.f32.f16.f16.f32 "
                 "{%0,%1,%2,%3}, {%4,%5,%6,%7}, {%8,%9}, {%0,%1,%2,%3};"
                 : "+f"(c[0]), "+f"(c[1]), "+f"(c[2]), "+f"(c[3])
                 : "r"(a[0]), "r"(a[1]), "r"(a[2]), "r"(a[3]), "r"(b[0]), "r"(b[1]));
}

// ---------------- grid barrier (monotonic epoch) -----------------------------
__device__ __forceinline__ unsigned ld_epoch() {
    unsigned e;
    asm volatile("ld.acquire.gpu.global.u32 %0, [%1];" : "=r"(e) : "l"(&g_epoch));
    return e;
}
__device__ __forceinline__ void grid_barrier(unsigned target) {
    __threadfence();
    __syncthreads();
    if (threadIdx.x == 0) {
        unsigned old;
        asm volatile("atom.add.release.gpu.global.u32 %0, [%1], 1;"
                     : "=r"(old) : "l"(&g_count) : "memory");
        if (old == NCTA - 1) {
            g_count = 0;
            asm volatile("red.release.gpu.global.add.u32 [%0], 1;"
                         :: "l"(&g_epoch) : "memory");
        } else {
            while ((int)(ld_epoch() - target) < 0) { }
        }
    }
    __syncthreads();
}

// ---------------------------------------------------------------------------
// Setup: W' fp16, h-major columns: W'[n'=h*5+g][k] = fp16(Ws[k][g*256+h])
// ---------------------------------------------------------------------------
__global__ __launch_bounds__(256) void split_ws_kernel(const float* __restrict__ Ws) {
    int idx = blockIdx.x * 256 + threadIdx.x;
    if (idx >= FIVEH * 512) return;
    int np = idx >> 9, k = idx & 511;
    int h = np / 5, g = np % 5;
    g_Wh[idx] = __float2half(Ws[k * FIVEH + g * H_ + h]);
}

// ---------------------------------------------------------------------------
// Precompute: PX = x@Wx_top, PY = y@Wx_bot (fp32 SIMT, gate-major cols)
// ---------------------------------------------------------------------------
__global__ __launch_bounds__(256) void precompute_kernel(
    const float* __restrict__ x, const float* __restrict__ y,
    const float* __restrict__ Wx)
{
    const int cell = blockIdx.x, n0 = blockIdx.y * 128, which = blockIdx.z;
    const float* A = which ? y : x;
    const int koff = which ? F_ : 0;
    float* P = which ? g_PY : g_PX;

    __shared__ float As[16][68];
    __shared__ float Bs[16][128];
    const int t = threadIdx.x;
    const int tx = t & 15, ty = t >> 4;
    const int lm = t >> 2, lk = (t & 3) * 4;

    float acc[4][8];
#pragma unroll
    for (int r = 0; r < 4; r++)
#pragma unroll
        for (int q = 0; q < 8; q++) acc[r][q] = 0.f;

    for (int k0 = 0; k0 < F_; k0 += 16) {
        float4 av = *(const float4*)&A[(lm * I_ + cell) * F_ + k0 + lk];
        As[lk + 0][lm] = av.x; As[lk + 1][lm] = av.y;
        As[lk + 2][lm] = av.z; As[lk + 3][lm] = av.w;
#pragma unroll
        for (int s = 0; s < 2; s++) {
            int idx = t + 256 * s;
            int kl = idx >> 5, c4 = idx & 31;
            *(float4*)&Bs[kl][c4 * 4] =
                *(const float4*)&Wx[(koff + k0 + kl) * FIVEH + n0 + c4 * 4];
        }
        __syncthreads();
#pragma unroll
        for (int k = 0; k < 16; k++) {
            float4 a4 = *(const float4*)&As[k][ty * 4];
            float4 b0 = *(const float4*)&Bs[k][tx * 8];
            float4 b1 = *(const float4*)&Bs[k][tx * 8 + 4];
            float a[4] = {a4.x, a4.y, a4.z, a4.w};
            float bb[8] = {b0.x, b0.y, b0.z, b0.w, b1.x, b1.y, b1.z, b1.w};
#pragma unroll
            for (int r = 0; r < 4; r++)
#pragma unroll
                for (int q = 0; q < 8; q++) acc[r][q] += a[r] * bb[q];
        }
        __syncthreads();
    }
#pragma unroll
    for (int r = 0; r < 4; r++) {
        int m = ty * 4 + r;
        float* dst = &P[(cell * B_ + m) * FIVEH + n0 + tx * 8];
        *(float4*)dst       = make_float4(acc[r][0], acc[r][1], acc[r][2], acc[r][3]);
        *(float4*)(dst + 4) = make_float4(acc[r][4], acc[r][5], acc[r][6], acc[r][7]);
    }
}

// ---------------------------------------------------------------------------
// Fused tile (weight-stationary): cell i, CTA-resident htile.
// M=64 batches, N=160 (32h x 5g), K <= 1024 (hor/ver halves skipped at edges,
// each half = 4 chunks of 64k, with hi+lo A passes sharing resident B).
// ---------------------------------------------------------------------------
__device__ __forceinline__ void fused_tile(
    char* smem, uint32_t sb,
    const float* __restrict__ bias, float* __restrict__ out,
    int d, int i, int htile)
{
    const int t = threadIdx.x, wid = t >> 5, lane = t & 31;
    const int j = d - i;
    const int prv = (d & 1) ^ 1, cur = d & 1;
    const bool hh = (i > 0), vv = (j > 0);

    const __half* __restrict__ Shp = g_Shi[prv];
    const __half* __restrict__ Slp = g_Slo[prv];

    __syncthreads();   // protect smem A/epilogue region across tasks

    // active k-chunks
    int scs[8], nsc = 0;
    if (hh) { scs[0] = 0; scs[1] = 1; scs[2] = 2; scs[3] = 3; nsc = 4; }
    if (vv) { scs[nsc] = 4; scs[nsc + 1] = 5; scs[nsc + 2] = 6; scs[nsc + 3] = 7; nsc += 4; }

    auto load_A = [&](int sc, int buf) {
        const int scell = (sc < 4) ? i - 1 : i;
        const int kc = (sc & 3) * 64;
        const uint32_t base = sb + W_TOT + buf * ASTAGE;
#pragma unroll
        for (int p = 0; p < 2; p++) {
            const __half* S = p ? Slp : Shp;
#pragma unroll
            for (int r = 0; r < 2; r++) {
                int idx = t + 256 * r;
                int b = idx >> 3, seg = idx & 7;
                cp16(base + p * APASS + b * 144 + seg * 16,
                     S + ((size_t)scell * B_ + b) * H_ + kc + seg * 8);
            }
        }
    };

    // warp tiling: 2m x 4n; warp tile m32 x n40
    const int wm = wid & 1, wn = wid >> 1;
    const int m0 = wm * 32, n0 = wn * 40;
    const uint32_t arow = (uint32_t)((m0 + ((lane >> 3) & 1) * 8 + (lane & 7)) * 144
                                     + (lane >> 4) * 16);
    const uint32_t brow = (uint32_t)((n0 + (lane & 7)) * 144 + ((lane >> 3) & 1) * 16);

    float acc[2][5][4];
#pragma unroll
    for (int f = 0; f < 2; f++)
#pragma unroll
        for (int e = 0; e < 5; e++)
#pragma unroll
            for (int q = 0; q < 4; q++) acc[f][e][q] = 0.f;

    if (nsc) {
        load_A(scs[0], 0);
        CP_COMMIT();

        for (int idx = 0; idx < nsc; idx++) {
            if (idx + 1 < nsc) {
                load_A(scs[idx + 1], (idx + 1) & 1);
                CP_COMMIT();
                CP_WAIT(1);
            } else {
                CP_WAIT(0);
            }
            __syncthreads();

            const int sc = scs[idx];
            const uint32_t abase = sb + W_TOT + (idx & 1) * ASTAGE;
            const uint32_t bbase = sb + sc * WCH;
#pragma unroll
            for (int ks = 0; ks < 4; ks++) {
                uint32_t bfr[5][2];
#pragma unroll
                for (int e = 0; e < 5; e++)
                    ldmB(bfr[e], bbase + brow + e * 1152 + ks * 32);
#pragma unroll
                for (int pass = 0; pass < 2; pass++) {
                    uint32_t afr[2][4];
#pragma unroll
                    for (int f = 0; f < 2; f++)
                        ldmA(afr[f], abase + pass * APASS + arow + f * 2304 + ks * 32);
#pragma unroll
                    for (int f = 0; f < 2; f++)
#pragma unroll
                        for (int e = 0; e < 5; e++)
                            mma16816(acc[f][e], afr[f], bfr[e]);
                }
            }
            if (idx + 1 < nsc) __syncthreads();
        }
    }

    // ---- epilogue: per-warp staging (16 rows x 40 cols), two f-stages ----
    __syncthreads();
    float* wbuf = (float*)(smem + W_TOT + wid * 2560);

    const float* __restrict__ Cp = g_C[prv];
    float* __restrict__ Cc = g_C[cur];
    __half* __restrict__ Shc = g_Shi[cur];
    __half* __restrict__ Slc = g_Slo[cur];

#pragma unroll
    for (int f = 0; f < 2; f++) {
        const int r0 = lane >> 2;
        const int c0 = (lane & 3) * 2;
#pragma unroll
        for (int e = 0; e < 5; e++) {
            wbuf[r0 * 40 + e * 8 + c0]           = acc[f][e][0];
            wbuf[r0 * 40 + e * 8 + c0 + 1]       = acc[f][e][1];
            wbuf[(r0 + 8) * 40 + e * 8 + c0]     = acc[f][e][2];
            wbuf[(r0 + 8) * 40 + e * 8 + c0 + 1] = acc[f][e][3];
        }
        __syncwarp();

#pragma unroll
        for (int it = 0; it < 4; it++) {
            const int item = lane * 4 + it;          // 0..127
            const int rr = item >> 3;                // 0..15
            const int hl8 = item & 7;
            const int b = m0 + f * 16 + rr;
            const int h = htile * 32 + wn * 8 + hl8;

            const float* PXr = g_PX + ((size_t)i * B_ + b) * FIVEH;
            const float* PYr = g_PY + ((size_t)j * B_ + b) * FIVEH;

            float pg[5];
#pragma unroll
            for (int g = 0; g < 5; g++) {
                const int col = g * H_ + h;
                pg[g] = wbuf[rr * 40 + hl8 * 5 + g] + PXr[col] + PYr[col] + bias[col];
            }
            float ch = hh ? Cp[(((i - 1) * B_) + b) * H_ + h] : 0.f;
            float cv = vv ? Cp[((i * B_) + b) * H_ + h] : 0.f;

            float ig = sigf(pg[0]);
            float fg = sigf(pg[1]);
            float og = sigf(pg[2]);
            float lg = sigf(pg[3]);
            float gg = tanhf(pg[4]);
            float c = fg * (lg * ch + (1.f - lg) * cv) + ig * gg;
            float s = og * tanhf(c);

            const size_t sidx = ((size_t)i * B_ + b) * H_ + h;
            Cc[sidx] = c;
            __half shi = __float2half(s);
            Shc[sidx] = shi;
            Slc[sidx] = __float2half(s - __half2float(shi));
            out[(((size_t)i * O_ + j) * B_ + b) * H_ + h] = s;
        }
        __syncwarp();
    }
}

// ---------------------------------------------------------------------------
// Persistent kernel: resident W' slab per CTA; 95 diagonals, 1 barrier each
// ---------------------------------------------------------------------------
__global__ __launch_bounds__(256, 1) void persist_kernel(
    const float* __restrict__ bias, float* __restrict__ out)
{
    extern __shared__ char smem[];
    const uint32_t sb = smem_u32(smem);
    const int t = threadIdx.x;
    const int htile = blockIdx.x & 7;
    const int qbase = (int)blockIdx.x >> 3;     // 0..17
    const int n_base = htile * 160;

    // ---- preload resident W' slab: 8 chunks x 160 rows x 64 fp16 ----
    for (int r = 0; r < 40; r++) {
        int idx = t + 256 * r;                  // 0..10239
        int sc = idx / 1280;
        int within = idx - sc * 1280;
        int row = within >> 3, seg = within & 7;
        cp16(sb + sc * WCH + row * 144 + seg * 16,
             g_Wh + (size_t)(n_base + row) * 512 + sc * 64 + seg * 8);
    }
    CP_COMMIT();
    CP_WAIT(0);
    __syncthreads();

    const unsigned epoch0 = ld_epoch();
    unsigned bars = 0;

    for (int d = 0; d < I_ + O_ - 1; d++) {
        const int i_lo = (d > O_ - 1) ? d - (O_ - 1) : 0;
        const int i_hi = (d < I_ - 1) ? d : I_ - 1;
        const int nv = i_hi - i_lo + 1;

        for (int q = qbase; q < nv; q += 18)
            fused_tile(smem, sb, bias, out, d, i_lo + q, htile);

        bars++; grid_barrier(epoch0 + bars);
    }
}

// ---------------------------------------------------------------------------
extern "C" void kernel_launch(void* const* d_in, const int* in_sizes, int n_in,
                              void* d_out, int out_size)
{
    const float* x  = (const float*)d_in[0];
    const float* y  = (const float*)d_in[1];
    const float* Wx = (const float*)d_in[2];
    const float* Ws = (const float*)d_in[3];
    const float* b  = (const float*)d_in[4];
    float* out = (float*)d_out;

    cudaFuncSetAttribute(persist_kernel, cudaFuncAttributeMaxDynamicSharedMemorySize,
                         SMEM_TOTAL);

    split_ws_kernel<<<(FIVEH * 512 + 255) / 256, 256>>>(Ws);
    precompute_kernel<<<dim3(I_, FIVEH / 128, 2), 256>>>(x, y, Wx);
    persist_kernel<<<NCTA, 256, SMEM_TOTAL>>>(b, out);
}

// round 8
// speedup vs baseline: 1.8725x; 1.8725x over previous
#include <cuda_runtime.h>
#include <cuda_fp16.h>
#include <stdint.h>
#include <math.h>

#define B_    64
#define I_    48
#define O_    48
#define F_    256
#define H_    256
#define FIVEH 1280
#define NCTA  148

// smem per stage: B tile 160x64 fp16 (rows stride 144B) + A 64x64 fp16
#define BBYTES 23040                 // 160*144
#define APASS  9216                  // 64*144
#define STAGE  (BBYTES + APASS)      // 32256
#define SMEM_TOTAL (2*STAGE)         // 64512 (epilogue reuse: 64*160*4 = 40960)

// ---------------- scratch (device globals) ----------------------------------
__device__ float g_PX[I_ * B_ * FIVEH];          // [i][b][g*256+h]
__device__ float g_PY[O_ * B_ * FIVEH];
__device__ __half g_Wh[FIVEH * 512];             // W' fp16, [n'][k], n'=h*5+g
__device__ __half g_S[2][I_ * B_ * H_];          // s state fp16, dbl-buffered
__device__ float  g_C[2][I_ * B_ * H_];
__device__ unsigned g_count;
__device__ unsigned g_epoch;

__device__ __forceinline__ float sigf(float x) { return 1.0f / (1.0f + expf(-x)); }

__device__ __forceinline__ uint32_t smem_u32(const void* p) {
    uint32_t a;
    asm("{ .reg .u64 t; cvta.to.shared.u64 t, %1; cvt.u32.u64 %0, t; }" : "=r"(a) : "l"(p));
    return a;
}
__device__ __forceinline__ void cp16(uint32_t dst, const void* src) {
    asm volatile("cp.async.cg.shared.global [%0], [%1], 16;"
                 :: "r"(dst), "l"(src) : "memory");
}
#define CP_COMMIT() asm volatile("cp.async.commit_group;" ::: "memory")
#define CP_WAIT(n)  asm volatile("cp.async.wait_group %0;" :: "n"(n) : "memory")

__device__ __forceinline__ void ldmA(uint32_t* a, uint32_t addr) {
    asm volatile("ldmatrix.sync.aligned.m8n8.x4.shared.b16 {%0,%1,%2,%3}, [%4];"
                 : "=r"(a[0]), "=r"(a[1]), "=r"(a[2]), "=r"(a[3]) : "r"(addr));
}
__device__ __forceinline__ void ldmB(uint32_t* b, uint32_t addr) {
    asm volatile("ldmatrix.sync.aligned.m8n8.x2.shared.b16 {%0,%1}, [%2];"
                 : "=r"(b[0]), "=r"(b[1]) : "r"(addr));
}
__device__ __forceinline__ void mma16816(float* c, const uint32_t* a, const uint32_t* b) {
    asm volatile("mma.sync.aligned.m16n8k16.row.col.f32.f16.f16.f32 "
                 "{%0,%1,%2,%3}, {%4,%5,%6,%7}, {%8,%9}, {%0,%1,%2,%3};"
                 : "+f"(c[0]), "+f"(c[1]), "+f"(c[2]), "+f"(c[3])
                 : "r"(a[0]), "r"(a[1]), "r"(a[2]), "r"(a[3]), "r"(b[0]), "r"(b[1]));
}

// ---------------- grid barrier (monotonic epoch) -----------------------------
__device__ __forceinline__ unsigned ld_epoch() {
    unsigned e;
    asm volatile("ld.acquire.gpu.global.u32 %0, [%1];" : "=r"(e) : "l"(&g_epoch));
    return e;
}
__device__ __forceinline__ void grid_barrier(unsigned target) {
    __threadfence();
    __syncthreads();
    if (threadIdx.x == 0) {
        unsigned old;
        asm volatile("atom.add.release.gpu.global.u32 %0, [%1], 1;"
                     : "=r"(old) : "l"(&g_count) : "memory");
        if (old == NCTA - 1) {
            g_count = 0;
            asm volatile("red.release.gpu.global.add.u32 [%0], 1;"
                         :: "l"(&g_epoch) : "memory");
        } else {
            while ((int)(ld_epoch() - target) < 0) { }
        }
    }
    __syncthreads();
}

// ---------------------------------------------------------------------------
// Setup: W' fp16, h-major columns: W'[n'=h*5+g][k] = fp16(Ws[k][g*256+h])
// ---------------------------------------------------------------------------
__global__ __launch_bounds__(256) void split_ws_kernel(const float* __restrict__ Ws) {
    int idx = blockIdx.x * 256 + threadIdx.x;
    if (idx >= FIVEH * 512) return;
    int np = idx >> 9, k = idx & 511;
    int h = np / 5, g = np % 5;
    g_Wh[idx] = __float2half(Ws[k * FIVEH + g * H_ + h]);
}

// ---------------------------------------------------------------------------
// Precompute: PX = x@Wx_top, PY = y@Wx_bot (fp32 SIMT, gate-major cols)
// ---------------------------------------------------------------------------
__global__ __launch_bounds__(256) void precompute_kernel(
    const float* __restrict__ x, const float* __restrict__ y,
    const float* __restrict__ Wx)
{
    const int cell = blockIdx.x, n0 = blockIdx.y * 128, which = blockIdx.z;
    const float* A = which ? y : x;
    const int koff = which ? F_ : 0;
    float* P = which ? g_PY : g_PX;

    __shared__ float As[16][68];
    __shared__ float Bs[16][128];
    const int t = threadIdx.x;
    const int tx = t & 15, ty = t >> 4;
    const int lm = t >> 2, lk = (t & 3) * 4;

    float acc[4][8];
#pragma unroll
    for (int r = 0; r < 4; r++)
#pragma unroll
        for (int q = 0; q < 8; q++) acc[r][q] = 0.f;

    for (int k0 = 0; k0 < F_; k0 += 16) {
        float4 av = *(const float4*)&A[(lm * I_ + cell) * F_ + k0 + lk];
        As[lk + 0][lm] = av.x; As[lk + 1][lm] = av.y;
        As[lk + 2][lm] = av.z; As[lk + 3][lm] = av.w;
#pragma unroll
        for (int s = 0; s < 2; s++) {
            int idx = t + 256 * s;
            int kl = idx >> 5, c4 = idx & 31;
            *(float4*)&Bs[kl][c4 * 4] =
                *(const float4*)&Wx[(koff + k0 + kl) * FIVEH + n0 + c4 * 4];
        }
        __syncthreads();
#pragma unroll
        for (int k = 0; k < 16; k++) {
            float4 a4 = *(const float4*)&As[k][ty * 4];
            float4 b0 = *(const float4*)&Bs[k][tx * 8];
            float4 b1 = *(const float4*)&Bs[k][tx * 8 + 4];
            float a[4] = {a4.x, a4.y, a4.z, a4.w};
            float bb[8] = {b0.x, b0.y, b0.z, b0.w, b1.x, b1.y, b1.z, b1.w};
#pragma unroll
            for (int r = 0; r < 4; r++)
#pragma unroll
                for (int q = 0; q < 8; q++) acc[r][q] += a[r] * bb[q];
        }
        __syncthreads();
    }
#pragma unroll
    for (int r = 0; r < 4; r++) {
        int m = ty * 4 + r;
        float* dst = &P[(cell * B_ + m) * FIVEH + n0 + tx * 8];
        *(float4*)dst       = make_float4(acc[r][0], acc[r][1], acc[r][2], acc[r][3]);
        *(float4*)(dst + 4) = make_float4(acc[r][4], acc[r][5], acc[r][6], acc[r][7]);
    }
}

// ---------------------------------------------------------------------------
// Fused tile: one cell (M=64 batches) x 32-h slice (N=160 = 32h x 5 gates),
// K = 512 single-term fp16 (s@W), hor/ver 256-k halves skipped at edges.
// ---------------------------------------------------------------------------
__device__ __forceinline__ void fused_tile(
    char* smem, uint32_t sb,
    const float* __restrict__ bias, float* __restrict__ out,
    int d, int i, int htile)
{
    const int t = threadIdx.x, wid = t >> 5, lane = t & 31;
    const int j = d - i;
    const int prv = (d & 1) ^ 1, cur = d & 1;
    const bool hh = (i > 0), vv = (j > 0);
    const int n_base = htile * 160;

    const __half* __restrict__ Sp = g_S[prv];

    __syncthreads();   // protect smem reuse across tasks

    // active 64-k chunks (sc 0..3 hor, 4..7 ver)
    int scs[8], nsc = 0;
    if (hh) { scs[0] = 0; scs[1] = 1; scs[2] = 2; scs[3] = 3; nsc = 4; }
    if (vv) { scs[nsc] = 4; scs[nsc + 1] = 5; scs[nsc + 2] = 6; scs[nsc + 3] = 7; nsc += 4; }

    auto load_chunk = [&](int sc, int buf) {
        const uint32_t base = sb + buf * STAGE;
        const int kb = sc * 64;               // W' k index
        const int scell = (sc < 4) ? i - 1 : i;
        const int kc = (sc & 3) * 64;         // column within the 256-wide state
        // B: 160 rows x 64 k
#pragma unroll
        for (int p = 0; p < 5; p++) {
            int idx = t + 256 * p;
            int r = idx >> 3, seg = idx & 7;
            cp16(base + r * 144 + seg * 16,
                 g_Wh + (size_t)(n_base + r) * 512 + kb + seg * 8);
        }
        // A: 64 rows x 64 k
#pragma unroll
        for (int p = 0; p < 2; p++) {
            int idx = t + 256 * p;
            int b = idx >> 3, seg = idx & 7;
            cp16(base + BBYTES + b * 144 + seg * 16,
                 Sp + ((size_t)scell * B_ + b) * H_ + kc + seg * 8);
        }
    };

    // warp tiling: 2m x 4n; warp tile m32 x n40
    const int wm = wid & 1, wn = wid >> 1;
    const int m0 = wm * 32, n0 = wn * 40;
    const uint32_t arow = (uint32_t)(BBYTES + (m0 + ((lane >> 3) & 1) * 8 + (lane & 7)) * 144
                                     + (lane >> 4) * 16);
    const uint32_t brow = (uint32_t)((n0 + (lane & 7)) * 144 + ((lane >> 3) & 1) * 16);

    float acc[2][5][4];
#pragma unroll
    for (int f = 0; f < 2; f++)
#pragma unroll
        for (int e = 0; e < 5; e++)
#pragma unroll
            for (int q = 0; q < 4; q++) acc[f][e][q] = 0.f;

    if (nsc) {
        load_chunk(scs[0], 0);
        CP_COMMIT();

        for (int idx = 0; idx < nsc; idx++) {
            if (idx + 1 < nsc) {
                load_chunk(scs[idx + 1], (idx + 1) & 1);
                CP_COMMIT();
                CP_WAIT(1);
            } else {
                CP_WAIT(0);
            }
            __syncthreads();

            const uint32_t base = sb + (idx & 1) * STAGE;
#pragma unroll
            for (int ks = 0; ks < 4; ks++) {
                uint32_t bfr[5][2];
#pragma unroll
                for (int e = 0; e < 5; e++)
                    ldmB(bfr[e], base + brow + e * 1152 + ks * 32);
                uint32_t afr[2][4];
#pragma unroll
                for (int f = 0; f < 2; f++)
                    ldmA(afr[f], base + arow + f * 2304 + ks * 32);
#pragma unroll
                for (int f = 0; f < 2; f++)
#pragma unroll
                    for (int e = 0; e < 5; e++)
                        mma16816(acc[f][e], afr[f], bfr[e]);
            }
            if (idx + 1 < nsc) __syncthreads();
        }
    }

    // ---- epilogue: acc -> smem pre [64 rows][160 n'] ----
    __syncthreads();
    float* pre = (float*)smem;
#pragma unroll
    for (int f = 0; f < 2; f++) {
#pragma unroll
        for (int e = 0; e < 5; e++) {
            int row = m0 + f * 16 + (lane >> 2);
            int col = n0 + e * 8 + (lane & 3) * 2;
            *(float2*)&pre[row * 160 + col]       = make_float2(acc[f][e][0], acc[f][e][1]);
            *(float2*)&pre[(row + 8) * 160 + col] = make_float2(acc[f][e][2], acc[f][e][3]);
        }
    }
    __syncthreads();

    // ---- gate math: 2048 items = 64 b x 32 h ----
    const float* __restrict__ Cp = g_C[prv];
    float* __restrict__ Cc = g_C[cur];
    __half* __restrict__ Sc = g_S[cur];

#pragma unroll
    for (int p = 0; p < 8; p++) {
        const int id = t + 256 * p;
        const int b = id >> 5, hl = id & 31;
        const int h = htile * 32 + hl;

        const float* PXr = g_PX + ((size_t)i * B_ + b) * FIVEH;
        const float* PYr = g_PY + ((size_t)j * B_ + b) * FIVEH;

        float pg[5];
#pragma unroll
        for (int g = 0; g < 5; g++) {
            const int col = g * H_ + h;
            pg[g] = pre[b * 160 + hl * 5 + g] + PXr[col] + PYr[col] + bias[col];
        }
        float ch = hh ? Cp[(((i - 1) * B_) + b) * H_ + h] : 0.f;
        float cv = vv ? Cp[((i * B_) + b) * H_ + h] : 0.f;

        float ig = sigf(pg[0]);
        float fg = sigf(pg[1]);
        float og = sigf(pg[2]);
        float lg = sigf(pg[3]);
        float gg = tanhf(pg[4]);
        float c = fg * (lg * ch + (1.f - lg) * cv) + ig * gg;
        float s = og * tanhf(c);

        const size_t sidx = ((size_t)i * B_ + b) * H_ + h;
        Cc[sidx] = c;
        Sc[sidx] = __float2half(s);
        out[(((size_t)i * O_ + j) * B_ + b) * H_ + h] = s;
    }
}

// ---------------------------------------------------------------------------
// Persistent kernel: 95 diagonals, task-strided fused tiles, 1 barrier each
// ---------------------------------------------------------------------------
__global__ __launch_bounds__(256, 1) void persist_kernel(
    const float* __restrict__ bias, float* __restrict__ out)
{
    extern __shared__ char smem[];
    const uint32_t sb = smem_u32(smem);

    const unsigned epoch0 = ld_epoch();
    unsigned bars = 0;

    for (int d = 0; d < I_ + O_ - 1; d++) {
        const int i_lo = (d > O_ - 1) ? d - (O_ - 1) : 0;
        const int i_hi = (d < I_ - 1) ? d : I_ - 1;
        const int nv = i_hi - i_lo + 1;

        const int ntasks = nv * 8;
        for (int task = blockIdx.x; task < ntasks; task += NCTA) {
            const int q = task >> 3;
            const int htile = task & 7;
            fused_tile(smem, sb, bias, out, d, i_lo + q, htile);
        }
        bars++; grid_barrier(epoch0 + bars);
    }
}

// ---------------------------------------------------------------------------
extern "C" void kernel_launch(void* const* d_in, const int* in_sizes, int n_in,
                              void* d_out, int out_size)
{
    const float* x  = (const float*)d_in[0];
    const float* y  = (const float*)d_in[1];
    const float* Wx = (const float*)d_in[2];
    const float* Ws = (const float*)d_in[3];
    const float* b  = (const float*)d_in[4];
    float* out = (float*)d_out;

    cudaFuncSetAttribute(persist_kernel, cudaFuncAttributeMaxDynamicSharedMemorySize,
                         SMEM_TOTAL);

    split_ws_kernel<<<(FIVEH * 512 + 255) / 256, 256>>>(Ws);
    precompute_kernel<<<dim3(I_, FIVEH / 128, 2), 256>>>(x, y, Wx);
    persist_kernel<<<NCTA, 256, SMEM_TOTAL>>>(b, out);
}

// round 9
// speedup vs baseline: 2.2534x; 1.2034x over previous
#include <cuda_runtime.h>
#include <cuda_fp16.h>
#include <stdint.h>
#include <math.h>

#define B_    64
#define I_    48
#define O_    48
#define F_    256
#define H_    256
#define FIVEH 1280
#define NCTA  296               // 2 CTAs per SM, 148 SMs

// smem per stage: B tile 160x64 fp16 (rows stride 144B) + A 64x64 fp16
#define BBYTES 23040                 // 160*144
#define APASS  9216                  // 64*144
#define STAGE  (BBYTES + APASS)      // 32256
#define SMEM_TOTAL (2*STAGE)         // 64512 (epilogue reuse: 64*160*4 = 40960)

// ---------------- scratch (device globals) ----------------------------------
__device__ float g_PX[I_ * B_ * FIVEH];          // [i][b][g*256+h]
__device__ float g_PY[O_ * B_ * FIVEH];
__device__ __half g_Wh[FIVEH * 512];             // W' fp16, [n'][k], n'=h*5+g
__device__ __half g_S[2][I_ * B_ * H_];          // s state fp16, dbl-buffered
__device__ float  g_C[2][I_ * B_ * H_];
__device__ unsigned g_count;
__device__ unsigned g_epoch;

__device__ __forceinline__ float sigf(float x) { return 1.0f / (1.0f + expf(-x)); }

__device__ __forceinline__ uint32_t smem_u32(const void* p) {
    uint32_t a;
    asm("{ .reg .u64 t; cvta.to.shared.u64 t, %1; cvt.u32.u64 %0, t; }" : "=r"(a) : "l"(p));
    return a;
}
__device__ __forceinline__ void cp16(uint32_t dst, const void* src) {
    asm volatile("cp.async.cg.shared.global [%0], [%1], 16;"
                 :: "r"(dst), "l"(src) : "memory");
}
#define CP_COMMIT() asm volatile("cp.async.commit_group;" ::: "memory")
#define CP_WAIT(n)  asm volatile("cp.async.wait_group %0;" :: "n"(n) : "memory")

__device__ __forceinline__ void ldmA(uint32_t* a, uint32_t addr) {
    asm volatile("ldmatrix.sync.aligned.m8n8.x4.shared.b16 {%0,%1,%2,%3}, [%4];"
                 : "=r"(a[0]), "=r"(a[1]), "=r"(a[2]), "=r"(a[3]) : "r"(addr));
}
__device__ __forceinline__ void ldmB(uint32_t* b, uint32_t addr) {
    asm volatile("ldmatrix.sync.aligned.m8n8.x2.shared.b16 {%0,%1}, [%2];"
                 : "=r"(b[0]), "=r"(b[1]) : "r"(addr));
}
__device__ __forceinline__ void mma16816(float* c, const uint32_t* a, const uint32_t* b) {
    asm volatile("mma.sync.aligned.m16n8k16.row.col.f32.f16.f16.f32 "
                 "{%0,%1,%2,%3}, {%4,%5,%6,%7}, {%8,%9}, {%0,%1,%2,%3};"
                 : "+f"(c[0]), "+f"(c[1]), "+f"(c[2]), "+f"(c[3])
                 : "r"(a[0]), "r"(a[1]), "r"(a[2]), "r"(a[3]), "r"(b[0]), "r"(b[1]));
}

// ---------------- grid barrier (monotonic epoch; release/acquire only) -------
__device__ __forceinline__ unsigned ld_epoch() {
    unsigned e;
    asm volatile("ld.acquire.gpu.global.u32 %0, [%1];" : "=r"(e) : "l"(&g_epoch));
    return e;
}
__device__ __forceinline__ void grid_barrier(unsigned target) {
    __syncthreads();
    if (threadIdx.x == 0) {
        unsigned old;
        // release-atomic orders ALL prior writes of this CTA before the arrive
        asm volatile("atom.add.release.gpu.global.u32 %0, [%1], 1;"
                     : "=r"(old) : "l"(&g_count) : "memory");
        if (old == NCTA - 1) {
            g_count = 0;
            asm volatile("red.release.gpu.global.add.u32 [%0], 1;"
                         :: "l"(&g_epoch) : "memory");
        } else {
            while ((int)(ld_epoch() - target) < 0) { }
        }
    }
    __syncthreads();
}

// ---------------------------------------------------------------------------
// Setup: W' fp16, h-major columns: W'[n'=h*5+g][k] = fp16(Ws[k][g*256+h])
// ---------------------------------------------------------------------------
__global__ __launch_bounds__(256) void split_ws_kernel(const float* __restrict__ Ws) {
    int idx = blockIdx.x * 256 + threadIdx.x;
    if (idx >= FIVEH * 512) return;
    int np = idx >> 9, k = idx & 511;
    int h = np / 5, g = np % 5;
    g_Wh[idx] = __float2half(Ws[k * FIVEH + g * H_ + h]);
}

// ---------------------------------------------------------------------------
// Precompute: PX = x@Wx_top, PY = y@Wx_bot (fp32 SIMT, gate-major cols)
// ---------------------------------------------------------------------------
__global__ __launch_bounds__(256) void precompute_kernel(
    const float* __restrict__ x, const float* __restrict__ y,
    const float* __restrict__ Wx)
{
    const int cell = blockIdx.x, n0 = blockIdx.y * 128, which = blockIdx.z;
    const float* A = which ? y : x;
    const int koff = which ? F_ : 0;
    float* P = which ? g_PY : g_PX;

    __shared__ float As[16][68];
    __shared__ float Bs[16][128];
    const int t = threadIdx.x;
    const int tx = t & 15, ty = t >> 4;
    const int lm = t >> 2, lk = (t & 3) * 4;

    float acc[4][8];
#pragma unroll
    for (int r = 0; r < 4; r++)
#pragma unroll
        for (int q = 0; q < 8; q++) acc[r][q] = 0.f;

    for (int k0 = 0; k0 < F_; k0 += 16) {
        float4 av = *(const float4*)&A[(lm * I_ + cell) * F_ + k0 + lk];
        As[lk + 0][lm] = av.x; As[lk + 1][lm] = av.y;
        As[lk + 2][lm] = av.z; As[lk + 3][lm] = av.w;
#pragma unroll
        for (int s = 0; s < 2; s++) {
            int idx = t + 256 * s;
            int kl = idx >> 5, c4 = idx & 31;
            *(float4*)&Bs[kl][c4 * 4] =
                *(const float4*)&Wx[(koff + k0 + kl) * FIVEH + n0 + c4 * 4];
        }
        __syncthreads();
#pragma unroll
        for (int k = 0; k < 16; k++) {
            float4 a4 = *(const float4*)&As[k][ty * 4];
            float4 b0 = *(const float4*)&Bs[k][tx * 8];
            float4 b1 = *(const float4*)&Bs[k][tx * 8 + 4];
            float a[4] = {a4.x, a4.y, a4.z, a4.w};
            float bb[8] = {b0.x, b0.y, b0.z, b0.w, b1.x, b1.y, b1.z, b1.w};
#pragma unroll
            for (int r = 0; r < 4; r++)
#pragma unroll
                for (int q = 0; q < 8; q++) acc[r][q] += a[r] * bb[q];
        }
        __syncthreads();
    }
#pragma unroll
    for (int r = 0; r < 4; r++) {
        int m = ty * 4 + r;
        float* dst = &P[(cell * B_ + m) * FIVEH + n0 + tx * 8];
        *(float4*)dst       = make_float4(acc[r][0], acc[r][1], acc[r][2], acc[r][3]);
        *(float4*)(dst + 4) = make_float4(acc[r][4], acc[r][5], acc[r][6], acc[r][7]);
    }
}

// ---------------------------------------------------------------------------
// Fused tile: one cell (M=64 batches) x 32-h slice (N=160 = 32h x 5 gates),
// K = 512 single-term fp16 (s@W), hor/ver 256-k halves skipped at edges.
// ---------------------------------------------------------------------------
__device__ __forceinline__ void fused_tile(
    char* smem, uint32_t sb,
    const float* __restrict__ bias, float* __restrict__ out,
    int d, int i, int htile)
{
    const int t = threadIdx.x, wid = t >> 5, lane = t & 31;
    const int j = d - i;
    const int prv = (d & 1) ^ 1, cur = d & 1;
    const bool hh = (i > 0), vv = (j > 0);
    const int n_base = htile * 160;

    const __half* __restrict__ Sp = g_S[prv];

    __syncthreads();   // protect smem reuse across tasks

    // active 64-k chunks (sc 0..3 hor, 4..7 ver)
    int scs[8], nsc = 0;
    if (hh) { scs[0] = 0; scs[1] = 1; scs[2] = 2; scs[3] = 3; nsc = 4; }
    if (vv) { scs[nsc] = 4; scs[nsc + 1] = 5; scs[nsc + 2] = 6; scs[nsc + 3] = 7; nsc += 4; }

    auto load_chunk = [&](int sc, int buf) {
        const uint32_t base = sb + buf * STAGE;
        const int kb = sc * 64;               // W' k index
        const int scell = (sc < 4) ? i - 1 : i;
        const int kc = (sc & 3) * 64;         // column within the 256-wide state
        // B: 160 rows x 64 k
#pragma unroll
        for (int p = 0; p < 5; p++) {
            int idx = t + 256 * p;
            int r = idx >> 3, seg = idx & 7;
            cp16(base + r * 144 + seg * 16,
                 g_Wh + (size_t)(n_base + r) * 512 + kb + seg * 8);
        }
        // A: 64 rows x 64 k
#pragma unroll
        for (int p = 0; p < 2; p++) {
            int idx = t + 256 * p;
            int b = idx >> 3, seg = idx & 7;
            cp16(base + BBYTES + b * 144 + seg * 16,
                 Sp + ((size_t)scell * B_ + b) * H_ + kc + seg * 8);
        }
    };

    // warp tiling: 2m x 4n; warp tile m32 x n40
    const int wm = wid & 1, wn = wid >> 1;
    const int m0 = wm * 32, n0 = wn * 40;
    const uint32_t arow = (uint32_t)(BBYTES + (m0 + ((lane >> 3) & 1) * 8 + (lane & 7)) * 144
                                     + (lane >> 4) * 16);
    const uint32_t brow = (uint32_t)((n0 + (lane & 7)) * 144 + ((lane >> 3) & 1) * 16);

    float acc[2][5][4];
#pragma unroll
    for (int f = 0; f < 2; f++)
#pragma unroll
        for (int e = 0; e < 5; e++)
#pragma unroll
            for (int q = 0; q < 4; q++) acc[f][e][q] = 0.f;

    if (nsc) {
        load_chunk(scs[0], 0);
        CP_COMMIT();

        for (int idx = 0; idx < nsc; idx++) {
            if (idx + 1 < nsc) {
                load_chunk(scs[idx + 1], (idx + 1) & 1);
                CP_COMMIT();
                CP_WAIT(1);
            } else {
                CP_WAIT(0);
            }
            __syncthreads();

            const uint32_t base = sb + (idx & 1) * STAGE;
#pragma unroll
            for (int ks = 0; ks < 4; ks++) {
                uint32_t bfr[5][2];
#pragma unroll
                for (int e = 0; e < 5; e++)
                    ldmB(bfr[e], base + brow + e * 1152 + ks * 32);
                uint32_t afr[2][4];
#pragma unroll
                for (int f = 0; f < 2; f++)
                    ldmA(afr[f], base + arow + f * 2304 + ks * 32);
#pragma unroll
                for (int f = 0; f < 2; f++)
#pragma unroll
                    for (int e = 0; e < 5; e++)
                        mma16816(acc[f][e], afr[f], bfr[e]);
            }
            if (idx + 1 < nsc) __syncthreads();
        }
    }

    // ---- epilogue: acc -> smem pre [64 rows][160 n'] ----
    __syncthreads();
    float* pre = (float*)smem;
#pragma unroll
    for (int f = 0; f < 2; f++) {
#pragma unroll
        for (int e = 0; e < 5; e++) {
            int row = m0 + f * 16 + (lane >> 2);
            int col = n0 + e * 8 + (lane & 3) * 2;
            *(float2*)&pre[row * 160 + col]       = make_float2(acc[f][e][0], acc[f][e][1]);
            *(float2*)&pre[(row + 8) * 160 + col] = make_float2(acc[f][e][2], acc[f][e][3]);
        }
    }
    __syncthreads();

    // ---- gate math: 2048 items = 64 b x 32 h ----
    const float* __restrict__ Cp = g_C[prv];
    float* __restrict__ Cc = g_C[cur];
    __half* __restrict__ Sc = g_S[cur];

#pragma unroll
    for (int p = 0; p < 8; p++) {
        const int id = t + 256 * p;
        const int b = id >> 5, hl = id & 31;
        const int h = htile * 32 + hl;

        const float* PXr = g_PX + ((size_t)i * B_ + b) * FIVEH;
        const float* PYr = g_PY + ((size_t)j * B_ + b) * FIVEH;

        float pg[5];
#pragma unroll
        for (int g = 0; g < 5; g++) {
            const int col = g * H_ + h;
            pg[g] = pre[b * 160 + hl * 5 + g] + PXr[col] + PYr[col] + bias[col];
        }
        float ch = hh ? Cp[(((i - 1) * B_) + b) * H_ + h] : 0.f;
        float cv = vv ? Cp[((i * B_) + b) * H_ + h] : 0.f;

        float ig = sigf(pg[0]);
        float fg = sigf(pg[1]);
        float og = sigf(pg[2]);
        float lg = sigf(pg[3]);
        float gg = tanhf(pg[4]);
        float c = fg * (lg * ch + (1.f - lg) * cv) + ig * gg;
        float s = og * tanhf(c);

        const size_t sidx = ((size_t)i * B_ + b) * H_ + h;
        Cc[sidx] = c;
        Sc[sidx] = __float2half(s);
        out[(((size_t)i * O_ + j) * B_ + b) * H_ + h] = s;
    }
}

// ---------------------------------------------------------------------------
// Persistent kernel: 95 diagonals, task-strided fused tiles, 1 barrier each
// ---------------------------------------------------------------------------
__global__ __launch_bounds__(256, 2) void persist_kernel(
    const float* __restrict__ bias, float* __restrict__ out)
{
    extern __shared__ char smem[];
    const uint32_t sb = smem_u32(smem);

    const unsigned epoch0 = ld_epoch();
    unsigned bars = 0;

    for (int d = 0; d < I_ + O_ - 1; d++) {
        const int i_lo = (d > O_ - 1) ? d - (O_ - 1) : 0;
        const int i_hi = (d < I_ - 1) ? d : I_ - 1;
        const int nv = i_hi - i_lo + 1;

        const int ntasks = nv * 8;
        for (int task = blockIdx.x; task < ntasks; task += NCTA) {
            const int q = task >> 3;
            const int htile = task & 7;
            fused_tile(smem, sb, bias, out, d, i_lo + q, htile);
        }
        bars++; grid_barrier(epoch0 + bars);
    }
}

// ---------------------------------------------------------------------------
extern "C" void kernel_launch(void* const* d_in, const int* in_sizes, int n_in,
                              void* d_out, int out_size)
{
    const float* x  = (const float*)d_in[0];
    const float* y  = (const float*)d_in[1];
    const float* Wx = (const float*)d_in[2];
    const float* Ws = (const float*)d_in[3];
    const float* b  = (const float*)d_in[4];
    float* out = (float*)d_out;

    cudaFuncSetAttribute(persist_kernel, cudaFuncAttributeMaxDynamicSharedMemorySize,
                         SMEM_TOTAL);

    split_ws_kernel<<<(FIVEH * 512 + 255) / 256, 256>>>(Ws);
    precompute_kernel<<<dim3(I_, FIVEH / 128, 2), 256>>>(x, y, Wx);
    persist_kernel<<<NCTA, 256, SMEM_TOTAL>>>(b, out);
}

// round 10
// speedup vs baseline: 2.5087x; 1.1133x over previous
#include <cuda_runtime.h>
#include <cuda_fp16.h>
#include <stdint.h>
#include <math.h>

#define B_    64
#define I_    48
#define O_    48
#define F_    256
#define H_    256
#define FIVEH 1280
#define NCTA  296               // 2 CTAs per SM

// smem per stage: B tile 160x64 fp16 (rows stride 144B) + A 64x64 fp16
#define BBYTES 23040                 // 160*144
#define APASS  9216                  // 64*144
#define STAGE  (BBYTES + APASS)      // 32256
#define SMEM_TOTAL (2*STAGE)         // 64512 (epilogue reuse: 64*160*4 = 40960)

#define CELLS (I_ * O_)              // 2304

// ---------------- scratch (device globals) ----------------------------------
__device__ float g_PX[I_ * B_ * FIVEH];          // [i][b][g*256+h]
__device__ float g_PY[O_ * B_ * FIVEH];
__device__ __half g_Wh[FIVEH * 512];             // W' fp16, [n'][k], n'=h*5+g
__device__ __half g_S16[(size_t)CELLS * B_ * H_];// s per cell (i*O+j), fp16
__device__ float  g_C[(size_t)CELLS * B_ * H_];  // c per cell, fp32
__device__ unsigned g_cnt[CELLS];                // per-cell completion counters

__device__ __forceinline__ float sigf(float x) { return 1.0f / (1.0f + expf(-x)); }

__device__ __forceinline__ uint32_t smem_u32(const void* p) {
    uint32_t a;
    asm("{ .reg .u64 t; cvta.to.shared.u64 t, %1; cvt.u32.u64 %0, t; }" : "=r"(a) : "l"(p));
    return a;
}
__device__ __forceinline__ void cp16(uint32_t dst, const void* src) {
    asm volatile("cp.async.cg.shared.global [%0], [%1], 16;"
                 :: "r"(dst), "l"(src) : "memory");
}
#define CP_COMMIT() asm volatile("cp.async.commit_group;" ::: "memory")
#define CP_WAIT(n)  asm volatile("cp.async.wait_group %0;" :: "n"(n) : "memory")

__device__ __forceinline__ void ldmA(uint32_t* a, uint32_t addr) {
    asm volatile("ldmatrix.sync.aligned.m8n8.x4.shared.b16 {%0,%1,%2,%3}, [%4];"
                 : "=r"(a[0]), "=r"(a[1]), "=r"(a[2]), "=r"(a[3]) : "r"(addr));
}
__device__ __forceinline__ void ldmB(uint32_t* b, uint32_t addr) {
    asm volatile("ldmatrix.sync.aligned.m8n8.x2.shared.b16 {%0,%1}, [%2];"
                 : "=r"(b[0]), "=r"(b[1]) : "r"(addr));
}
__device__ __forceinline__ void mma16816(float* c, const uint32_t* a, const uint32_t* b) {
    asm volatile("mma.sync.aligned.m16n8k16.row.col.f32.f16.f16.f32 "
                 "{%0,%1,%2,%3}, {%4,%5,%6,%7}, {%8,%9}, {%0,%1,%2,%3};"
                 : "+f"(c[0]), "+f"(c[1]), "+f"(c[2]), "+f"(c[3])
                 : "r"(a[0]), "r"(a[1]), "r"(a[2]), "r"(a[3]), "r"(b[0]), "r"(b[1]));
}

// ---------------- dataflow flag helpers --------------------------------------
__device__ __forceinline__ void wait_cell(const unsigned* p) {
    unsigned v;
    do {
        asm volatile("ld.acquire.gpu.global.u32 %0, [%1];" : "=r"(v) : "l"(p));
    } while (v < 8u);
}
__device__ __forceinline__ void signal_cell(unsigned* p) {
    asm volatile("red.release.gpu.global.add.u32 [%0], 1;" :: "l"(p) : "memory");
}

// ---------------------------------------------------------------------------
// Setup kernels
// ---------------------------------------------------------------------------
__global__ void zero_cnt_kernel() {
    int idx = blockIdx.x * 256 + threadIdx.x;
    if (idx < CELLS) g_cnt[idx] = 0u;
}

__global__ __launch_bounds__(256) void split_ws_kernel(const float* __restrict__ Ws) {
    int idx = blockIdx.x * 256 + threadIdx.x;
    if (idx >= FIVEH * 512) return;
    int np = idx >> 9, k = idx & 511;
    int h = np / 5, g = np % 5;
    g_Wh[idx] = __float2half(Ws[k * FIVEH + g * H_ + h]);
}

__global__ __launch_bounds__(256) void precompute_kernel(
    const float* __restrict__ x, const float* __restrict__ y,
    const float* __restrict__ Wx)
{
    const int cell = blockIdx.x, n0 = blockIdx.y * 128, which = blockIdx.z;
    const float* A = which ? y : x;
    const int koff = which ? F_ : 0;
    float* P = which ? g_PY : g_PX;

    __shared__ float As[16][68];
    __shared__ float Bs[16][128];
    const int t = threadIdx.x;
    const int tx = t & 15, ty = t >> 4;
    const int lm = t >> 2, lk = (t & 3) * 4;

    float acc[4][8];
#pragma unroll
    for (int r = 0; r < 4; r++)
#pragma unroll
        for (int q = 0; q < 8; q++) acc[r][q] = 0.f;

    for (int k0 = 0; k0 < F_; k0 += 16) {
        float4 av = *(const float4*)&A[(lm * I_ + cell) * F_ + k0 + lk];
        As[lk + 0][lm] = av.x; As[lk + 1][lm] = av.y;
        As[lk + 2][lm] = av.z; As[lk + 3][lm] = av.w;
#pragma unroll
        for (int s = 0; s < 2; s++) {
            int idx = t + 256 * s;
            int kl = idx >> 5, c4 = idx & 31;
            *(float4*)&Bs[kl][c4 * 4] =
                *(const float4*)&Wx[(koff + k0 + kl) * FIVEH + n0 + c4 * 4];
        }
        __syncthreads();
#pragma unroll
        for (int k = 0; k < 16; k++) {
            float4 a4 = *(const float4*)&As[k][ty * 4];
            float4 b0 = *(const float4*)&Bs[k][tx * 8];
            float4 b1 = *(const float4*)&Bs[k][tx * 8 + 4];
            float a[4] = {a4.x, a4.y, a4.z, a4.w};
            float bb[8] = {b0.x, b0.y, b0.z, b0.w, b1.x, b1.y, b1.z, b1.w};
#pragma unroll
            for (int r = 0; r < 4; r++)
#pragma unroll
                for (int q = 0; q < 8; q++) acc[r][q] += a[r] * bb[q];
        }
        __syncthreads();
    }
#pragma unroll
    for (int r = 0; r < 4; r++) {
        int m = ty * 4 + r;
        float* dst = &P[(cell * B_ + m) * FIVEH + n0 + tx * 8];
        *(float4*)dst       = make_float4(acc[r][0], acc[r][1], acc[r][2], acc[r][3]);
        *(float4*)(dst + 4) = make_float4(acc[r][4], acc[r][5], acc[r][6], acc[r][7]);
    }
}

// ---------------------------------------------------------------------------
// Fused tile: cell (i,j) x 32-h slice; waits on neighbor cells' flags.
// K = 512 single-term fp16 (s@W), hor/ver 256-k halves skipped at edges.
// ---------------------------------------------------------------------------
__device__ __forceinline__ void fused_tile(
    char* smem, uint32_t sb,
    const float* __restrict__ bias, float* __restrict__ out,
    int i, int j, int htile)
{
    const int t = threadIdx.x, wid = t >> 5, lane = t & 31;
    const bool hh = (i > 0), vv = (j > 0);
    const int n_base = htile * 160;
    const int cell  = i * O_ + j;
    const int cellH = cell - O_;      // (i-1, j)
    const int cellV = cell - 1;       // (i, j-1)

    const __half* __restrict__ SH = g_S16 + (size_t)cellH * (B_ * H_);
    const __half* __restrict__ SV = g_S16 + (size_t)cellV * (B_ * H_);

    // ---- dependency wait (also separates smem reuse across tasks) ----
    __syncthreads();
    if (t == 0) {
        if (hh) wait_cell(&g_cnt[cellH]);
        if (vv) wait_cell(&g_cnt[cellV]);
    }
    __syncthreads();

    // active 64-k chunks (sc 0..3 hor, 4..7 ver)
    int scs[8], nsc = 0;
    if (hh) { scs[0] = 0; scs[1] = 1; scs[2] = 2; scs[3] = 3; nsc = 4; }
    if (vv) { scs[nsc] = 4; scs[nsc + 1] = 5; scs[nsc + 2] = 6; scs[nsc + 3] = 7; nsc += 4; }

    auto load_chunk = [&](int sc, int buf) {
        const uint32_t base = sb + buf * STAGE;
        const int kb = sc * 64;               // W' k index
        const __half* S = (sc < 4) ? SH : SV;
        const int kc = (sc & 3) * 64;         // column within the 256-wide state
        // B: 160 rows x 64 k
#pragma unroll
        for (int p = 0; p < 5; p++) {
            int idx = t + 256 * p;
            int r = idx >> 3, seg = idx & 7;
            cp16(base + r * 144 + seg * 16,
                 g_Wh + (size_t)(n_base + r) * 512 + kb + seg * 8);
        }
        // A: 64 rows x 64 k
#pragma unroll
        for (int p = 0; p < 2; p++) {
            int idx = t + 256 * p;
            int b = idx >> 3, seg = idx & 7;
            cp16(base + BBYTES + b * 144 + seg * 16,
                 S + (size_t)b * H_ + kc + seg * 8);
        }
    };

    // warp tiling: 2m x 4n; warp tile m32 x n40
    const int wm = wid & 1, wn = wid >> 1;
    const int m0 = wm * 32, n0 = wn * 40;
    const uint32_t arow = (uint32_t)(BBYTES + (m0 + ((lane >> 3) & 1) * 8 + (lane & 7)) * 144
                                     + (lane >> 4) * 16);
    const uint32_t brow = (uint32_t)((n0 + (lane & 7)) * 144 + ((lane >> 3) & 1) * 16);

    float acc[2][5][4];
#pragma unroll
    for (int f = 0; f < 2; f++)
#pragma unroll
        for (int e = 0; e < 5; e++)
#pragma unroll
            for (int q = 0; q < 4; q++) acc[f][e][q] = 0.f;

    if (nsc) {
        load_chunk(scs[0], 0);
        CP_COMMIT();

        for (int idx = 0; idx < nsc; idx++) {
            if (idx + 1 < nsc) {
                load_chunk(scs[idx + 1], (idx + 1) & 1);
                CP_COMMIT();
                CP_WAIT(1);
            } else {
                CP_WAIT(0);
            }
            __syncthreads();

            const uint32_t base = sb + (idx & 1) * STAGE;
#pragma unroll
            for (int ks = 0; ks < 4; ks++) {
                uint32_t bfr[5][2];
#pragma unroll
                for (int e = 0; e < 5; e++)
                    ldmB(bfr[e], base + brow + e * 1152 + ks * 32);
                uint32_t afr[2][4];
#pragma unroll
                for (int f = 0; f < 2; f++)
                    ldmA(afr[f], base + arow + f * 2304 + ks * 32);
#pragma unroll
                for (int f = 0; f < 2; f++)
#pragma unroll
                    for (int e = 0; e < 5; e++)
                        mma16816(acc[f][e], afr[f], bfr[e]);
            }
            if (idx + 1 < nsc) __syncthreads();
        }
    }

    // ---- epilogue: acc -> smem pre [64 rows][160 n'] ----
    __syncthreads();
    float* pre = (float*)smem;
#pragma unroll
    for (int f = 0; f < 2; f++) {
#pragma unroll
        for (int e = 0; e < 5; e++) {
            int row = m0 + f * 16 + (lane >> 2);
            int col = n0 + e * 8 + (lane & 3) * 2;
            *(float2*)&pre[row * 160 + col]       = make_float2(acc[f][e][0], acc[f][e][1]);
            *(float2*)&pre[(row + 8) * 160 + col] = make_float2(acc[f][e][2], acc[f][e][3]);
        }
    }
    __syncthreads();

    // ---- gate math: 2048 items = 64 b x 32 h ----
    const float* __restrict__ CH = g_C + (size_t)cellH * (B_ * H_);
    const float* __restrict__ CV = g_C + (size_t)cellV * (B_ * H_);
    float*  __restrict__ Cc = g_C   + (size_t)cell  * (B_ * H_);
    __half* __restrict__ Sc = g_S16 + (size_t)cell  * (B_ * H_);

#pragma unroll
    for (int p = 0; p < 8; p++) {
        const int id = t + 256 * p;
        const int b = id >> 5, hl = id & 31;
        const int h = htile * 32 + hl;

        const float* PXr = g_PX + ((size_t)i * B_ + b) * FIVEH;
        const float* PYr = g_PY + ((size_t)j * B_ + b) * FIVEH;

        float pg[5];
#pragma unroll
        for (int g = 0; g < 5; g++) {
            const int col = g * H_ + h;
            pg[g] = pre[b * 160 + hl * 5 + g] + PXr[col] + PYr[col] + bias[col];
        }
        float ch = hh ? CH[(size_t)b * H_ + h] : 0.f;
        float cv = vv ? CV[(size_t)b * H_ + h] : 0.f;

        float ig = sigf(pg[0]);
        float fg = sigf(pg[1]);
        float og = sigf(pg[2]);
        float lg = sigf(pg[3]);
        float gg = tanhf(pg[4]);
        float c = fg * (lg * ch + (1.f - lg) * cv) + ig * gg;
        float s = og * tanhf(c);

        const size_t sidx = (size_t)b * H_ + h;
        Cc[sidx] = c;
        Sc[sidx] = __float2half(s);
        out[(((size_t)i * O_ + j) * B_ + b) * H_ + h] = s;
    }

    // ---- publish: all writes visible, then arrive on this cell's counter ----
    __threadfence();
    __syncthreads();
    if (t == 0) signal_cell(&g_cnt[cell]);
}

// ---------------------------------------------------------------------------
// Persistent kernel: NO grid barriers — pure dataflow over 18432 tile tasks,
// enumerated in diagonal order, strided across CTAs (deadlock-free: each
// CTA's list is diagonal-ordered; deps live strictly earlier in the order).
// ---------------------------------------------------------------------------
__global__ __launch_bounds__(256, 2) void persist_kernel(
    const float* __restrict__ bias, float* __restrict__ out)
{
    extern __shared__ char smem[];
    const uint32_t sb = smem_u32(smem);

    int base = 0;
    int next = blockIdx.x;

    for (int d = 0; d < I_ + O_ - 1; d++) {
        const int i_lo = (d > O_ - 1) ? d - (O_ - 1) : 0;
        const int i_hi = (d < I_ - 1) ? d : I_ - 1;
        const int nv = i_hi - i_lo + 1;
        const int ntasks = nv * 8;

        while (next < base + ntasks) {
            const int local = next - base;
            const int q = local >> 3;
            const int htile = local & 7;
            const int i = i_lo + q;
            fused_tile(smem, sb, bias, out, i, d - i, htile);
            next += NCTA;
        }
        base += ntasks;
    }
}

// ---------------------------------------------------------------------------
extern "C" void kernel_launch(void* const* d_in, const int* in_sizes, int n_in,
                              void* d_out, int out_size)
{
    const float* x  = (const float*)d_in[0];
    const float* y  = (const float*)d_in[1];
    const float* Wx = (const float*)d_in[2];
    const float* Ws = (const float*)d_in[3];
    const float* b  = (const float*)d_in[4];
    float* out = (float*)d_out;

    cudaFuncSetAttribute(persist_kernel, cudaFuncAttributeMaxDynamicSharedMemorySize,
                         SMEM_TOTAL);

    zero_cnt_kernel<<<(CELLS + 255) / 256, 256>>>();
    split_ws_kernel<<<(FIVEH * 512 + 255) / 256, 256>>>(Ws);
    precompute_kernel<<<dim3(I_, FIVEH / 128, 2), 256>>>(x, y, Wx);
    persist_kernel<<<NCTA, 256, SMEM_TOTAL>>>(b, out);
}

// round 11
// speedup vs baseline: 2.9026x; 1.1570x over previous
#include <cuda_runtime.h>
#include <cuda_fp16.h>
#include <stdint.h>
#include <math.h>

#define B_    64
#define I_    48
#define O_    48
#define F_    256
#define H_    256
#define FIVEH 1280
#define NCTA  296               // 2 CTAs per SM

// smem per stage: B tile 160x64 fp16 (rows stride 144B) + A 64x64 fp16
#define BBYTES 23040                 // 160*144
#define APASS  9216                  // 64*144
#define STAGE  (BBYTES + APASS)      // 32256
#define SMEM_TOTAL (2*STAGE)         // 64512 (epilogue reuse: 64*160*4 = 40960)

#define CELLS (I_ * O_)              // 2304

// ---------------- scratch (device globals) ----------------------------------
__device__ float g_PX[I_ * B_ * FIVEH];          // [i][b][g*256+h]
__device__ float g_PY[O_ * B_ * FIVEH];
__device__ __half g_Wh[FIVEH * 512];             // W' fp16, [n'][k], n'=h*5+g
__device__ __half g_S16[(size_t)CELLS * B_ * H_];// s per cell (i*O+j), fp16
__device__ float  g_C[(size_t)CELLS * B_ * H_];  // c per cell, fp32
__device__ unsigned g_cnt[CELLS];                // per-cell completion counters

__device__ __forceinline__ float sigf(float x) { return 1.0f / (1.0f + expf(-x)); }

__device__ __forceinline__ uint32_t smem_u32(const void* p) {
    uint32_t a;
    asm("{ .reg .u64 t; cvta.to.shared.u64 t, %1; cvt.u32.u64 %0, t; }" : "=r"(a) : "l"(p));
    return a;
}
__device__ __forceinline__ void cp16(uint32_t dst, const void* src) {
    asm volatile("cp.async.cg.shared.global [%0], [%1], 16;"
                 :: "r"(dst), "l"(src) : "memory");
}
#define CP_COMMIT() asm volatile("cp.async.commit_group;" ::: "memory")
#define CP_WAIT(n)  asm volatile("cp.async.wait_group %0;" :: "n"(n) : "memory")

__device__ __forceinline__ void ldmA(uint32_t* a, uint32_t addr) {
    asm volatile("ldmatrix.sync.aligned.m8n8.x4.shared.b16 {%0,%1,%2,%3}, [%4];"
                 : "=r"(a[0]), "=r"(a[1]), "=r"(a[2]), "=r"(a[3]) : "r"(addr));
}
__device__ __forceinline__ void ldmB(uint32_t* b, uint32_t addr) {
    asm volatile("ldmatrix.sync.aligned.m8n8.x2.shared.b16 {%0,%1}, [%2];"
                 : "=r"(b[0]), "=r"(b[1]) : "r"(addr));
}
__device__ __forceinline__ void mma16816(float* c, const uint32_t* a, const uint32_t* b) {
    asm volatile("mma.sync.aligned.m16n8k16.row.col.f32.f16.f16.f32 "
                 "{%0,%1,%2,%3}, {%4,%5,%6,%7}, {%8,%9}, {%0,%1,%2,%3};"
                 : "+f"(c[0]), "+f"(c[1]), "+f"(c[2]), "+f"(c[3])
                 : "r"(a[0]), "r"(a[1]), "r"(a[2]), "r"(a[3]), "r"(b[0]), "r"(b[1]));
}

// ---------------- dataflow flag helpers --------------------------------------
__device__ __forceinline__ void wait_cell(const unsigned* p) {
    unsigned v;
    do {
        asm volatile("ld.acquire.gpu.global.u32 %0, [%1];" : "=r"(v) : "l"(p));
    } while (v < 8u);
}
__device__ __forceinline__ void signal_cell(unsigned* p) {
    asm volatile("red.release.gpu.global.add.u32 [%0], 1;" :: "l"(p) : "memory");
}

// ---------------------------------------------------------------------------
// Setup kernels
// ---------------------------------------------------------------------------
__global__ void zero_cnt_kernel() {
    int idx = blockIdx.x * 256 + threadIdx.x;
    if (idx < CELLS) g_cnt[idx] = 0u;
}

__global__ __launch_bounds__(256) void split_ws_kernel(const float* __restrict__ Ws) {
    int idx = blockIdx.x * 256 + threadIdx.x;
    if (idx >= FIVEH * 512) return;
    int np = idx >> 9, k = idx & 511;
    int h = np / 5, g = np % 5;
    g_Wh[idx] = __float2half(Ws[k * FIVEH + g * H_ + h]);
}

__global__ __launch_bounds__(256) void precompute_kernel(
    const float* __restrict__ x, const float* __restrict__ y,
    const float* __restrict__ Wx)
{
    const int cell = blockIdx.x, n0 = blockIdx.y * 128, which = blockIdx.z;
    const float* A = which ? y : x;
    const int koff = which ? F_ : 0;
    float* P = which ? g_PY : g_PX;

    __shared__ float As[16][68];
    __shared__ float Bs[16][128];
    const int t = threadIdx.x;
    const int tx = t & 15, ty = t >> 4;
    const int lm = t >> 2, lk = (t & 3) * 4;

    float acc[4][8];
#pragma unroll
    for (int r = 0; r < 4; r++)
#pragma unroll
        for (int q = 0; q < 8; q++) acc[r][q] = 0.f;

    for (int k0 = 0; k0 < F_; k0 += 16) {
        float4 av = *(const float4*)&A[(lm * I_ + cell) * F_ + k0 + lk];
        As[lk + 0][lm] = av.x; As[lk + 1][lm] = av.y;
        As[lk + 2][lm] = av.z; As[lk + 3][lm] = av.w;
#pragma unroll
        for (int s = 0; s < 2; s++) {
            int idx = t + 256 * s;
            int kl = idx >> 5, c4 = idx & 31;
            *(float4*)&Bs[kl][c4 * 4] =
                *(const float4*)&Wx[(koff + k0 + kl) * FIVEH + n0 + c4 * 4];
        }
        __syncthreads();
#pragma unroll
        for (int k = 0; k < 16; k++) {
            float4 a4 = *(const float4*)&As[k][ty * 4];
            float4 b0 = *(const float4*)&Bs[k][tx * 8];
            float4 b1 = *(const float4*)&Bs[k][tx * 8 + 4];
            float a[4] = {a4.x, a4.y, a4.z, a4.w};
            float bb[8] = {b0.x, b0.y, b0.z, b0.w, b1.x, b1.y, b1.z, b1.w};
#pragma unroll
            for (int r = 0; r < 4; r++)
#pragma unroll
                for (int q = 0; q < 8; q++) acc[r][q] += a[r] * bb[q];
        }
        __syncthreads();
    }
#pragma unroll
    for (int r = 0; r < 4; r++) {
        int m = ty * 4 + r;
        float* dst = &P[(cell * B_ + m) * FIVEH + n0 + tx * 8];
        *(float4*)dst       = make_float4(acc[r][0], acc[r][1], acc[r][2], acc[r][3]);
        *(float4*)(dst + 4) = make_float4(acc[r][4], acc[r][5], acc[r][6], acc[r][7]);
    }
}

// ---------------------------------------------------------------------------
// Fused tile: cell (i,j) x 32-h slice; waits on neighbor cells' flags.
// K = 512 single-term fp16 (s@W), hor/ver 256-k halves skipped at edges.
// First B chunk prefetched BEFORE the dependency wait (weights have no deps).
// ---------------------------------------------------------------------------
__device__ __forceinline__ void fused_tile(
    char* smem, uint32_t sb,
    const float* __restrict__ bias, float* __restrict__ out,
    int i, int j, int htile)
{
    const int t = threadIdx.x, wid = t >> 5, lane = t & 31;
    const bool hh = (i > 0), vv = (j > 0);
    const int n_base = htile * 160;
    const int cell  = i * O_ + j;
    const int cellH = cell - O_;      // (i-1, j)
    const int cellV = cell - 1;       // (i, j-1)

    const __half* __restrict__ SH = g_S16 + (size_t)cellH * (B_ * H_);
    const __half* __restrict__ SV = g_S16 + (size_t)cellV * (B_ * H_);

    // active 64-k chunks (sc 0..3 hor, 4..7 ver)
    int scs[8], nsc = 0;
    if (hh) { scs[0] = 0; scs[1] = 1; scs[2] = 2; scs[3] = 3; nsc = 4; }
    if (vv) { scs[nsc] = 4; scs[nsc + 1] = 5; scs[nsc + 2] = 6; scs[nsc + 3] = 7; nsc += 4; }

    auto load_B = [&](int sc, int buf) {
        const uint32_t base = sb + buf * STAGE;
        const int kb = sc * 64;
#pragma unroll
        for (int p = 0; p < 5; p++) {
            int idx = t + 256 * p;
            int r = idx >> 3, seg = idx & 7;
            cp16(base + r * 144 + seg * 16,
                 g_Wh + (size_t)(n_base + r) * 512 + kb + seg * 8);
        }
    };
    auto load_A = [&](int sc, int buf) {
        const uint32_t base = sb + buf * STAGE;
        const __half* S = (sc < 4) ? SH : SV;
        const int kc = (sc & 3) * 64;
#pragma unroll
        for (int p = 0; p < 2; p++) {
            int idx = t + 256 * p;
            int b = idx >> 3, seg = idx & 7;
            cp16(base + BBYTES + b * 144 + seg * 16,
                 S + (size_t)b * H_ + kc + seg * 8);
        }
    };

    // ---- prefetch first B chunk (no deps), then dependency wait ----
    if (nsc) load_B(scs[0], 0);          // issued, not yet committed
    if (t == 0) {
        if (hh) wait_cell(&g_cnt[cellH]);
        if (vv) wait_cell(&g_cnt[cellV]);
    }
    __syncthreads();

    // warp tiling: 2m x 4n; warp tile m32 x n40
    const int wm = wid & 1, wn = wid >> 1;
    const int m0 = wm * 32, n0 = wn * 40;
    const uint32_t arow = (uint32_t)(BBYTES + (m0 + ((lane >> 3) & 1) * 8 + (lane & 7)) * 144
                                     + (lane >> 4) * 16);
    const uint32_t brow = (uint32_t)((n0 + (lane & 7)) * 144 + ((lane >> 3) & 1) * 16);

    float acc[2][5][4];
#pragma unroll
    for (int f = 0; f < 2; f++)
#pragma unroll
        for (int e = 0; e < 5; e++)
#pragma unroll
            for (int q = 0; q < 4; q++) acc[f][e][q] = 0.f;

    if (nsc) {
        load_A(scs[0], 0);
        CP_COMMIT();                     // group: B0 + A0

        for (int idx = 0; idx < nsc; idx++) {
            if (idx + 1 < nsc) {
                load_B(scs[idx + 1], (idx + 1) & 1);
                load_A(scs[idx + 1], (idx + 1) & 1);
                CP_COMMIT();
                CP_WAIT(1);
            } else {
                CP_WAIT(0);
            }
            __syncthreads();

            const uint32_t base = sb + (idx & 1) * STAGE;
#pragma unroll
            for (int ks = 0; ks < 4; ks++) {
                uint32_t bfr[5][2];
#pragma unroll
                for (int e = 0; e < 5; e++)
                    ldmB(bfr[e], base + brow + e * 1152 + ks * 32);
                uint32_t afr[2][4];
#pragma unroll
                for (int f = 0; f < 2; f++)
                    ldmA(afr[f], base + arow + f * 2304 + ks * 32);
#pragma unroll
                for (int f = 0; f < 2; f++)
#pragma unroll
                    for (int e = 0; e < 5; e++)
                        mma16816(acc[f][e], afr[f], bfr[e]);
            }
            if (idx + 1 < nsc) __syncthreads();
        }
    }

    // ---- epilogue: acc -> smem pre [64 rows][160 n'] ----
    __syncthreads();
    float* pre = (float*)smem;
#pragma unroll
    for (int f = 0; f < 2; f++) {
#pragma unroll
        for (int e = 0; e < 5; e++) {
            int row = m0 + f * 16 + (lane >> 2);
            int col = n0 + e * 8 + (lane & 3) * 2;
            *(float2*)&pre[row * 160 + col]       = make_float2(acc[f][e][0], acc[f][e][1]);
            *(float2*)&pre[(row + 8) * 160 + col] = make_float2(acc[f][e][2], acc[f][e][3]);
        }
    }
    __syncthreads();

    // ---- gate math, vectorized: 512 items = 64 b x 8 h4-groups ----
    const float* __restrict__ CH = g_C + (size_t)cellH * (B_ * H_);
    const float* __restrict__ CV = g_C + (size_t)cellV * (B_ * H_);
    float*  __restrict__ Cc = g_C   + (size_t)cell  * (B_ * H_);
    __half* __restrict__ Sc = g_S16 + (size_t)cell  * (B_ * H_);

#pragma unroll
    for (int p = 0; p < 2; p++) {
        const int id = t + 256 * p;
        const int b = id >> 3;
        const int hl = (id & 7) * 4;
        const int h = htile * 32 + hl;

        const float* PXr = g_PX + ((size_t)i * B_ + b) * FIVEH;
        const float* PYr = g_PY + ((size_t)j * B_ + b) * FIVEH;

        float pg[5][4];
#pragma unroll
        for (int g = 0; g < 5; g++) {
            const int col = g * H_ + h;
            float4 px = *(const float4*)&PXr[col];
            float4 py = *(const float4*)&PYr[col];
            float4 bb = *(const float4*)&bias[col];
            pg[g][0] = pre[b * 160 + (hl + 0) * 5 + g] + px.x + py.x + bb.x;
            pg[g][1] = pre[b * 160 + (hl + 1) * 5 + g] + px.y + py.y + bb.y;
            pg[g][2] = pre[b * 160 + (hl + 2) * 5 + g] + px.z + py.z + bb.z;
            pg[g][3] = pre[b * 160 + (hl + 3) * 5 + g] + px.w + py.w + bb.w;
        }

        float4 ch4 = make_float4(0.f, 0.f, 0.f, 0.f);
        float4 cv4 = make_float4(0.f, 0.f, 0.f, 0.f);
        if (hh) ch4 = *(const float4*)&CH[(size_t)b * H_ + h];
        if (vv) cv4 = *(const float4*)&CV[(size_t)b * H_ + h];
        float ch[4] = {ch4.x, ch4.y, ch4.z, ch4.w};
        float cv[4] = {cv4.x, cv4.y, cv4.z, cv4.w};

        float so[4], co[4];
#pragma unroll
        for (int u = 0; u < 4; u++) {
            float ig = sigf(pg[0][u]);
            float fg = sigf(pg[1][u]);
            float og = sigf(pg[2][u]);
            float lg = sigf(pg[3][u]);
            float gg = tanhf(pg[4][u]);
            float c = fg * (lg * ch[u] + (1.f - lg) * cv[u]) + ig * gg;
            co[u] = c;
            so[u] = og * tanhf(c);
        }

        const size_t sidx = (size_t)b * H_ + h;
        *(float4*)&Cc[sidx] = make_float4(co[0], co[1], co[2], co[3]);
        __half sh[4];
#pragma unroll
        for (int u = 0; u < 4; u++) sh[u] = __float2half(so[u]);
        *(uint2*)&Sc[sidx] = *(uint2*)&sh[0];
        *(float4*)&out[(((size_t)i * O_ + j) * B_ + b) * H_ + h] =
            make_float4(so[0], so[1], so[2], so[3]);
    }

    // ---- publish: syncthreads orders CTA writes; release-add publishes ----
    __syncthreads();
    if (t == 0) signal_cell(&g_cnt[cell]);
}

// ---------------------------------------------------------------------------
// Persistent kernel: NO grid barriers — pure dataflow over 18432 tile tasks,
// enumerated in diagonal order, strided across CTAs (deadlock-free: each
// CTA's list is diagonal-ordered; deps live strictly earlier in the order).
// ---------------------------------------------------------------------------
__global__ __launch_bounds__(256, 2) void persist_kernel(
    const float* __restrict__ bias, float* __restrict__ out)
{
    extern __shared__ char smem[];
    const uint32_t sb = smem_u32(smem);

    int base = 0;
    int next = blockIdx.x;

    for (int d = 0; d < I_ + O_ - 1; d++) {
        const int i_lo = (d > O_ - 1) ? d - (O_ - 1) : 0;
        const int i_hi = (d < I_ - 1) ? d : I_ - 1;
        const int nv = i_hi - i_lo + 1;
        const int ntasks = nv * 8;

        while (next < base + ntasks) {
            const int local = next - base;
            const int q = local >> 3;
            const int htile = local & 7;
            const int i = i_lo + q;
            fused_tile(smem, sb, bias, out, i, d - i, htile);
            next += NCTA;
        }
        base += ntasks;
    }
}

// ---------------------------------------------------------------------------
extern "C" void kernel_launch(void* const* d_in, const int* in_sizes, int n_in,
                              void* d_out, int out_size)
{
    const float* x  = (const float*)d_in[0];
    const float* y  = (const float*)d_in[1];
    const float* Wx = (const float*)d_in[2];
    const float* Ws = (const float*)d_in[3];
    const float* b  = (const float*)d_in[4];
    float* out = (float*)d_out;

    cudaFuncSetAttribute(persist_kernel, cudaFuncAttributeMaxDynamicSharedMemorySize,
                         SMEM_TOTAL);

    zero_cnt_kernel<<<(CELLS + 255) / 256, 256>>>();
    split_ws_kernel<<<(FIVEH * 512 + 255) / 256, 256>>>(Ws);
    precompute_kernel<<<dim3(I_, FIVEH / 128, 2), 256>>>(x, y, Wx);
    persist_kernel<<<NCTA, 256, SMEM_TOTAL>>>(b, out);
}

// round 12
// speedup vs baseline: 3.0979x; 1.0673x over previous
#include <cuda_runtime.h>
#include <cuda_fp16.h>
#include <stdint.h>
#include <math.h>

#define B_    64
#define I_    48
#define O_    48
#define F_    256
#define H_    256
#define FIVEH 1280
#define NCTA  296               // 2 CTAs per SM

// smem per stage: B tile 160x64 fp16 (rows stride 144B) + A 64x64 fp16
#define BBYTES 23040                 // 160*144
#define APASS  9216                  // 64*144
#define STAGE  (BBYTES + APASS)      // 32256
#define NSTAGE 3
#define SMEM_TOTAL (NSTAGE*STAGE)    // 96768 (epilogue reuse: 64*160*4 = 40960)

#define CELLS (I_ * O_)              // 2304

// ---------------- scratch (device globals) ----------------------------------
__device__ float g_PX[I_ * B_ * FIVEH];          // [i][b][g*256+h]
__device__ float g_PY[O_ * B_ * FIVEH];
__device__ __half g_Wh[FIVEH * 512];             // W' fp16, [n'][k], n'=h*5+g
__device__ __half g_S16[(size_t)CELLS * B_ * H_];// s per cell (i*O+j), fp16
__device__ float  g_C[(size_t)CELLS * B_ * H_];  // c per cell, fp32
__device__ unsigned g_cnt[CELLS];                // per-cell completion counters

// ---------------- fast transcendentals (MUFU path) ---------------------------
__device__ __forceinline__ float sigf(float x) {
    return __fdividef(1.f, 1.f + __expf(-x));
}
__device__ __forceinline__ float tanhf_fast(float x) {
    float xc = fminf(fmaxf(x, -15.f), 15.f);
    float e = __expf(2.f * xc);
    return __fdividef(e - 1.f, e + 1.f);
}

__device__ __forceinline__ uint32_t smem_u32(const void* p) {
    uint32_t a;
    asm("{ .reg .u64 t; cvta.to.shared.u64 t, %1; cvt.u32.u64 %0, t; }" : "=r"(a) : "l"(p));
    return a;
}
__device__ __forceinline__ void cp16(uint32_t dst, const void* src) {
    asm volatile("cp.async.cg.shared.global [%0], [%1], 16;"
                 :: "r"(dst), "l"(src) : "memory");
}
#define CP_COMMIT() asm volatile("cp.async.commit_group;" ::: "memory")
#define CP_WAIT(n)  asm volatile("cp.async.wait_group %0;" :: "n"(n) : "memory")

__device__ __forceinline__ void ldmA(uint32_t* a, uint32_t addr) {
    asm volatile("ldmatrix.sync.aligned.m8n8.x4.shared.b16 {%0,%1,%2,%3}, [%4];"
                 : "=r"(a[0]), "=r"(a[1]), "=r"(a[2]), "=r"(a[3]) : "r"(addr));
}
__device__ __forceinline__ void ldmB(uint32_t* b, uint32_t addr) {
    asm volatile("ldmatrix.sync.aligned.m8n8.x2.shared.b16 {%0,%1}, [%2];"
                 : "=r"(b[0]), "=r"(b[1]) : "r"(addr));
}
__device__ __forceinline__ void mma16816(float* c, const uint32_t* a, const uint32_t* b) {
    asm volatile("mma.sync.aligned.m16n8k16.row.col.f32.f16.f16.f32 "
                 "{%0,%1,%2,%3}, {%4,%5,%6,%7}, {%8,%9}, {%0,%1,%2,%3};"
                 : "+f"(c[0]), "+f"(c[1]), "+f"(c[2]), "+f"(c[3])
                 : "r"(a[0]), "r"(a[1]), "r"(a[2]), "r"(a[3]), "r"(b[0]), "r"(b[1]));
}

// ---------------- dataflow flag helpers --------------------------------------
__device__ __forceinline__ void wait_cell(const unsigned* p) {
    unsigned v;
    do {
        asm volatile("ld.acquire.gpu.global.u32 %0, [%1];" : "=r"(v) : "l"(p));
    } while (v < 8u);
}
__device__ __forceinline__ void signal_cell(unsigned* p) {
    asm volatile("red.release.gpu.global.add.u32 [%0], 1;" :: "l"(p) : "memory");
}

// ---------------------------------------------------------------------------
// Setup kernels
// ---------------------------------------------------------------------------
__global__ void zero_cnt_kernel() {
    int idx = blockIdx.x * 256 + threadIdx.x;
    if (idx < CELLS) g_cnt[idx] = 0u;
}

__global__ __launch_bounds__(256) void split_ws_kernel(const float* __restrict__ Ws) {
    int idx = blockIdx.x * 256 + threadIdx.x;
    if (idx >= FIVEH * 512) return;
    int np = idx >> 9, k = idx & 511;
    int h = np / 5, g = np % 5;
    g_Wh[idx] = __float2half(Ws[k * FIVEH + g * H_ + h]);
}

__global__ __launch_bounds__(256) void precompute_kernel(
    const float* __restrict__ x, const float* __restrict__ y,
    const float* __restrict__ Wx)
{
    const int cell = blockIdx.x, n0 = blockIdx.y * 128, which = blockIdx.z;
    const float* A = which ? y : x;
    const int koff = which ? F_ : 0;
    float* P = which ? g_PY : g_PX;

    __shared__ float As[16][68];
    __shared__ float Bs[16][128];
    const int t = threadIdx.x;
    const int tx = t & 15, ty = t >> 4;
    const int lm = t >> 2, lk = (t & 3) * 4;

    float acc[4][8];
#pragma unroll
    for (int r = 0; r < 4; r++)
#pragma unroll
        for (int q = 0; q < 8; q++) acc[r][q] = 0.f;

    for (int k0 = 0; k0 < F_; k0 += 16) {
        float4 av = *(const float4*)&A[(lm * I_ + cell) * F_ + k0 + lk];
        As[lk + 0][lm] = av.x; As[lk + 1][lm] = av.y;
        As[lk + 2][lm] = av.z; As[lk + 3][lm] = av.w;
#pragma unroll
        for (int s = 0; s < 2; s++) {
            int idx = t + 256 * s;
            int kl = idx >> 5, c4 = idx & 31;
            *(float4*)&Bs[kl][c4 * 4] =
                *(const float4*)&Wx[(koff + k0 + kl) * FIVEH + n0 + c4 * 4];
        }
        __syncthreads();
#pragma unroll
        for (int k = 0; k < 16; k++) {
            float4 a4 = *(const float4*)&As[k][ty * 4];
            float4 b0 = *(const float4*)&Bs[k][tx * 8];
            float4 b1 = *(const float4*)&Bs[k][tx * 8 + 4];
            float a[4] = {a4.x, a4.y, a4.z, a4.w};
            float bb[8] = {b0.x, b0.y, b0.z, b0.w, b1.x, b1.y, b1.z, b1.w};
#pragma unroll
            for (int r = 0; r < 4; r++)
#pragma unroll
                for (int q = 0; q < 8; q++) acc[r][q] += a[r] * bb[q];
        }
        __syncthreads();
    }
#pragma unroll
    for (int r = 0; r < 4; r++) {
        int m = ty * 4 + r;
        float* dst = &P[(cell * B_ + m) * FIVEH + n0 + tx * 8];
        *(float4*)dst       = make_float4(acc[r][0], acc[r][1], acc[r][2], acc[r][3]);
        *(float4*)(dst + 4) = make_float4(acc[r][4], acc[r][5], acc[r][6], acc[r][7]);
    }
}

// ---------------------------------------------------------------------------
// Fused tile: cell (i,j) x 32-h slice; waits on neighbor cells' flags.
// K = 512 single-term fp16 (s@W), hor/ver 256-k halves skipped at edges.
// 3-stage cp.async pipeline; first B chunk prefetched BEFORE the flag wait.
// ---------------------------------------------------------------------------
__device__ __forceinline__ void fused_tile(
    char* smem, uint32_t sb,
    const float* __restrict__ bias, float* __restrict__ out,
    int i, int j, int htile)
{
    const int t = threadIdx.x, wid = t >> 5, lane = t & 31;
    const bool hh = (i > 0), vv = (j > 0);
    const int n_base = htile * 160;
    const int cell  = i * O_ + j;
    const int cellH = cell - O_;      // (i-1, j)
    const int cellV = cell - 1;       // (i, j-1)

    const __half* __restrict__ SH = g_S16 + (size_t)cellH * (B_ * H_);
    const __half* __restrict__ SV = g_S16 + (size_t)cellV * (B_ * H_);

    // active 64-k chunks (sc 0..3 hor, 4..7 ver)
    int scs[8], nsc = 0;
    if (hh) { scs[0] = 0; scs[1] = 1; scs[2] = 2; scs[3] = 3; nsc = 4; }
    if (vv) { scs[nsc] = 4; scs[nsc + 1] = 5; scs[nsc + 2] = 6; scs[nsc + 3] = 7; nsc += 4; }

    auto load_B = [&](int sc, int buf) {
        const uint32_t base = sb + buf * STAGE;
        const int kb = sc * 64;
#pragma unroll
        for (int p = 0; p < 5; p++) {
            int idx = t + 256 * p;
            int r = idx >> 3, seg = idx & 7;
            cp16(base + r * 144 + seg * 16,
                 g_Wh + (size_t)(n_base + r) * 512 + kb + seg * 8);
        }
    };
    auto load_A = [&](int sc, int buf) {
        const uint32_t base = sb + buf * STAGE;
        const __half* S = (sc < 4) ? SH : SV;
        const int kc = (sc & 3) * 64;
#pragma unroll
        for (int p = 0; p < 2; p++) {
            int idx = t + 256 * p;
            int b = idx >> 3, seg = idx & 7;
            cp16(base + BBYTES + b * 144 + seg * 16,
                 S + (size_t)b * H_ + kc + seg * 8);
        }
    };

    // ---- prefetch first B chunk (no deps), then dependency wait ----
    if (nsc) load_B(scs[0], 0);          // issued, not yet committed
    if (t == 0) {
        if (hh) wait_cell(&g_cnt[cellH]);
        if (vv) wait_cell(&g_cnt[cellV]);
    }
    __syncthreads();

    // warp tiling: 2m x 4n; warp tile m32 x n40
    const int wm = wid & 1, wn = wid >> 1;
    const int m0 = wm * 32, n0 = wn * 40;
    const uint32_t arow = (uint32_t)(BBYTES + (m0 + ((lane >> 3) & 1) * 8 + (lane & 7)) * 144
                                     + (lane >> 4) * 16);
    const uint32_t brow = (uint32_t)((n0 + (lane & 7)) * 144 + ((lane >> 3) & 1) * 16);

    float acc[2][5][4];
#pragma unroll
    for (int f = 0; f < 2; f++)
#pragma unroll
        for (int e = 0; e < 5; e++)
#pragma unroll
            for (int q = 0; q < 4; q++) acc[f][e][q] = 0.f;

    if (nsc) {
        // prologue: groups 0 and 1 in flight (nsc is 4 or 8)
        load_A(scs[0], 0);
        CP_COMMIT();                     // group 0: B0 + A0
        load_B(scs[1], 1);
        load_A(scs[1], 1);
        CP_COMMIT();                     // group 1

        int buf = 0, buf2 = 2;           // buf = idx%3, buf2 = (idx+2)%3
        for (int idx = 0; idx < nsc; idx++) {
            if (idx < nsc - 1) CP_WAIT(1);
            else               CP_WAIT(0);
            __syncthreads();

            if (idx + 2 < nsc) {         // prefetch depth 2
                load_B(scs[idx + 2], buf2);
                load_A(scs[idx + 2], buf2);
                CP_COMMIT();
            }

            const uint32_t base = sb + buf * STAGE;
#pragma unroll
            for (int ks = 0; ks < 4; ks++) {
                uint32_t bfr[5][2];
#pragma unroll
                for (int e = 0; e < 5; e++)
                    ldmB(bfr[e], base + brow + e * 1152 + ks * 32);
                uint32_t afr[2][4];
#pragma unroll
                for (int f = 0; f < 2; f++)
                    ldmA(afr[f], base + arow + f * 2304 + ks * 32);
#pragma unroll
                for (int f = 0; f < 2; f++)
#pragma unroll
                    for (int e = 0; e < 5; e++)
                        mma16816(acc[f][e], afr[f], bfr[e]);
            }
            if (++buf == NSTAGE) buf = 0;
            if (++buf2 == NSTAGE) buf2 = 0;
        }
    }

    // ---- epilogue: acc -> smem pre [64 rows][160 n'] ----
    __syncthreads();
    float* pre = (float*)smem;
#pragma unroll
    for (int f = 0; f < 2; f++) {
#pragma unroll
        for (int e = 0; e < 5; e++) {
            int row = m0 + f * 16 + (lane >> 2);
            int col = n0 + e * 8 + (lane & 3) * 2;
            *(float2*)&pre[row * 160 + col]       = make_float2(acc[f][e][0], acc[f][e][1]);
            *(float2*)&pre[(row + 8) * 160 + col] = make_float2(acc[f][e][2], acc[f][e][3]);
        }
    }
    __syncthreads();

    // ---- gate math, vectorized: 512 items = 64 b x 8 h4-groups ----
    const float* __restrict__ CH = g_C + (size_t)cellH * (B_ * H_);
    const float* __restrict__ CV = g_C + (size_t)cellV * (B_ * H_);
    float*  __restrict__ Cc = g_C   + (size_t)cell  * (B_ * H_);
    __half* __restrict__ Sc = g_S16 + (size_t)cell  * (B_ * H_);

    float sokeep[2][4];
    int   bkeep[2], hkeep[2];

#pragma unroll
    for (int p = 0; p < 2; p++) {
        const int id = t + 256 * p;
        const int b = id >> 3;
        const int hl = (id & 7) * 4;
        const int h = htile * 32 + hl;
        bkeep[p] = b; hkeep[p] = h;

        const float* PXr = g_PX + ((size_t)i * B_ + b) * FIVEH;
        const float* PYr = g_PY + ((size_t)j * B_ + b) * FIVEH;

        float pg[5][4];
#pragma unroll
        for (int g = 0; g < 5; g++) {
            const int col = g * H_ + h;
            float4 px = *(const float4*)&PXr[col];
            float4 py = *(const float4*)&PYr[col];
            float4 bb = *(const float4*)&bias[col];
            pg[g][0] = pre[b * 160 + (hl + 0) * 5 + g] + px.x + py.x + bb.x;
            pg[g][1] = pre[b * 160 + (hl + 1) * 5 + g] + px.y + py.y + bb.y;
            pg[g][2] = pre[b * 160 + (hl + 2) * 5 + g] + px.z + py.z + bb.z;
            pg[g][3] = pre[b * 160 + (hl + 3) * 5 + g] + px.w + py.w + bb.w;
        }

        float4 ch4 = make_float4(0.f, 0.f, 0.f, 0.f);
        float4 cv4 = make_float4(0.f, 0.f, 0.f, 0.f);
        if (hh) ch4 = *(const float4*)&CH[(size_t)b * H_ + h];
        if (vv) cv4 = *(const float4*)&CV[(size_t)b * H_ + h];
        float ch[4] = {ch4.x, ch4.y, ch4.z, ch4.w};
        float cv[4] = {cv4.x, cv4.y, cv4.z, cv4.w};

        float so[4], co[4];
#pragma unroll
        for (int u = 0; u < 4; u++) {
            float ig = sigf(pg[0][u]);
            float fg = sigf(pg[1][u]);
            float og = sigf(pg[2][u]);
            float lg = sigf(pg[3][u]);
            float gg = tanhf_fast(pg[4][u]);
            float c = fg * (lg * ch[u] + (1.f - lg) * cv[u]) + ig * gg;
            co[u] = c;
            so[u] = og * tanhf_fast(c);
            sokeep[p][u] = so[u];
        }

        const size_t sidx = (size_t)b * H_ + h;
        *(float4*)&Cc[sidx] = make_float4(co[0], co[1], co[2], co[3]);
        __half sh[4];
#pragma unroll
        for (int u = 0; u < 4; u++) sh[u] = __float2half(so[u]);
        *(uint2*)&Sc[sidx] = *(uint2*)&sh[0];
    }

    // ---- publish EARLY: consumers need only C and S16 ----
    __syncthreads();
    if (t == 0) signal_cell(&g_cnt[cell]);

    // ---- output store off the critical path ----
#pragma unroll
    for (int p = 0; p < 2; p++) {
        *(float4*)&out[(((size_t)i * O_ + j) * B_ + bkeep[p]) * H_ + hkeep[p]] =
            make_float4(sokeep[p][0], sokeep[p][1], sokeep[p][2], sokeep[p][3]);
    }
}

// ---------------------------------------------------------------------------
// Persistent kernel: NO grid barriers — pure dataflow over 18432 tile tasks,
// enumerated in diagonal order, strided across CTAs (deadlock-free: each
// CTA's list is diagonal-ordered; deps live strictly earlier in the order).
// ---------------------------------------------------------------------------
__global__ __launch_bounds__(256, 2) void persist_kernel(
    const float* __restrict__ bias, float* __restrict__ out)
{
    extern __shared__ char smem[];
    const uint32_t sb = smem_u32(smem);

    int base = 0;
    int next = blockIdx.x;

    for (int d = 0; d < I_ + O_ - 1; d++) {
        const int i_lo = (d > O_ - 1) ? d - (O_ - 1) : 0;
        const int i_hi = (d < I_ - 1) ? d : I_ - 1;
        const int nv = i_hi - i_lo + 1;
        const int ntasks = nv * 8;

        while (next < base + ntasks) {
            const int local = next - base;
            const int q = local >> 3;
            const int htile = local & 7;
            const int i = i_lo + q;
            fused_tile(smem, sb, bias, out, i, d - i, htile);
            next += NCTA;
        }
        base += ntasks;
    }
}

// ---------------------------------------------------------------------------
extern "C" void kernel_launch(void* const* d_in, const int* in_sizes, int n_in,
                              void* d_out, int out_size)
{
    const float* x  = (const float*)d_in[0];
    const float* y  = (const float*)d_in[1];
    const float* Wx = (const float*)d_in[2];
    const float* Ws = (const float*)d_in[3];
    const float* b  = (const float*)d_in[4];
    float* out = (float*)d_out;

    cudaFuncSetAttribute(persist_kernel, cudaFuncAttributeMaxDynamicSharedMemorySize,
                         SMEM_TOTAL);

    zero_cnt_kernel<<<(CELLS + 255) / 256, 256>>>();
    split_ws_kernel<<<(FIVEH * 512 + 255) / 256, 256>>>(Ws);
    precompute_kernel<<<dim3(I_, FIVEH / 128, 2), 256>>>(x, y, Wx);
    persist_kernel<<<NCTA, 256, SMEM_TOTAL>>>(b, out);
}